// round 10
// baseline (speedup 1.0000x reference)
#include <cuda_runtime.h>
#include <math.h>
#include <math_constants.h>

#define NN 50000
#define EE 640000
#define DIN 256
#define DD 128
#define HH 8
#define NCC 47
#define LL 3

// ---------------- scratch (static device allocations; no runtime alloc) ----
__device__ float g_h[NN * DD];
__device__ float g_agg[NN * DD];
__device__ float g_t[NN * 512];       // qkv [N,384] per layer; also ff1 [N,512]
__device__ float g_t2[NN * 512];      // agg@Wo [N,128]; ff2 [N,512]
__device__ float g_wqkv[LL * DD * 384];
__device__ int   g_deg[NN];
__device__ int   g_off[NN + 1];
__device__ int   g_cur[NN];
__device__ int   g_csr[EE];

// ---------------- CSR build ------------------------------------------------
__global__ void zero_deg_kernel() {
    int i = blockIdx.x * blockDim.x + threadIdx.x;
    if (i < NN) g_deg[i] = 0;
}

__global__ void count_deg_kernel(const int* __restrict__ dst) {
    int e = blockIdx.x * blockDim.x + threadIdx.x;
    if (e < EE) atomicAdd(&g_deg[dst[e]], 1);
}

__global__ void scan_kernel() {
    __shared__ int wsum[32];
    __shared__ int carry_s;
    int t = threadIdx.x, lane = t & 31, wid = t >> 5;
    if (t == 0) carry_s = 0;
    __syncthreads();
    for (int base = 0; base < NN; base += 1024) {
        int i = base + t;
        int val = (i < NN) ? g_deg[i] : 0;
        int incl = val;
        #pragma unroll
        for (int o = 1; o < 32; o <<= 1) {
            int x = __shfl_up_sync(0xFFFFFFFFu, incl, o);
            if (lane >= o) incl += x;
        }
        if (lane == 31) wsum[wid] = incl;
        __syncthreads();
        if (wid == 0) {
            int wv = wsum[lane];
            int wincl = wv;
            #pragma unroll
            for (int o = 1; o < 32; o <<= 1) {
                int x = __shfl_up_sync(0xFFFFFFFFu, wincl, o);
                if (lane >= o) wincl += x;
            }
            wsum[lane] = wincl - wv;
        }
        __syncthreads();
        int carry = carry_s;
        int excl = carry + wsum[wid] + incl - val;
        if (i < NN) { g_off[i] = excl; g_cur[i] = excl; }
        __syncthreads();
        if (t == 1023) carry_s = carry + wsum[31] + incl;
        __syncthreads();
    }
    if (threadIdx.x == 0) g_off[NN] = carry_s;
}

__global__ void scatter_kernel(const int* __restrict__ src, const int* __restrict__ dst) {
    int e = blockIdx.x * blockDim.x + threadIdx.x;
    if (e < EE) {
        int d = dst[e];
        int pos = atomicAdd(&g_cur[d], 1);
        g_csr[pos] = src[e];
    }
}

// ---------------- pack Wq|Wk|Wv -> [L][128][384] ---------------------------
__global__ void pack_qkv_kernel(const float* __restrict__ Wq,
                                const float* __restrict__ Wk,
                                const float* __restrict__ Wv) {
    int i = blockIdx.x * blockDim.x + threadIdx.x;
    if (i < LL * DD * DD) {
        int l = i / (DD * DD);
        int r = (i / DD) % DD;
        int c = i % DD;
        size_t o = ((size_t)l * DD + r) * 384;
        g_wqkv[o + c]       = Wq[i];
        g_wqkv[o + 128 + c] = Wk[i];
        g_wqkv[o + 256 + c] = Wv[i];
    }
}

// ---------------- TF32 tensor-core GEMM ------------------------------------
// BM=BN=128, BK=16, 256 threads, 8 warps 4(M)x2(N), 32x64 warp tile.
// Double-buffered; smem holds tiles in MMA FRAGMENT ORDER so each A fragment
// is one LDS.128 and each B fragment one LDS.64 (20 vector LDS per warp per
// K-step vs 48 scalar before -> LSU no longer the bottleneck).
//   aFrag[kbi(2)][tm16(8)][lane(32)][4]  (2048 u32)
//   bFrag[kbi(2)][tn8(16)][lane(32)][2]  (2048 u32)
__device__ __forceinline__ unsigned f2tf(float f) {
    unsigned u;
    asm("cvt.rna.tf32.f32 %0, %1;" : "=r"(u) : "f"(f));
    return u;
}

#define STG_U32 4096
#define GEMM_SMEM_BYTES (2 * STG_U32 * 4)

template <int BIAS, int RELU>
__global__ void __launch_bounds__(256)
tf32gemm_kernel(const float* __restrict__ A, const float* __restrict__ B,
                const float* __restrict__ bias, float* __restrict__ C,
                int M, int N, int K) {
    extern __shared__ unsigned sm[];   // [2][STG_U32]

    int tid = threadIdx.x, lane = tid & 31, wid = tid >> 5;
    int row0 = blockIdx.y * 128, col0 = blockIdx.x * 128;
    int wn = (wid >> 2) * 64;
    int g = lane >> 2, c = lane & 3;

    int aRow = tid >> 1, aSeg = tid & 1;   // A: row aRow, k-span aSeg*8..+7
    int bRow = tid >> 5;                   // B: rows bRow, bRow+8; cols lane*4..+3
    int gr = row0 + aRow;
    int gc = col0 + lane * 4;

    const bool nVec = ((N & 127) == 0);
    const bool nEven = ((N & 1) == 0);

    float acc[2][8][4];
    #pragma unroll
    for (int i = 0; i < 2; i++)
        #pragma unroll
        for (int j = 0; j < 8; j++)
            #pragma unroll
            for (int r = 0; r < 4; r++) acc[i][j][r] = 0.f;

    float4 pa0, pa1, pb0, pb1;

    auto fetch = [&](int k0) {
        pa0 = make_float4(0.f, 0.f, 0.f, 0.f); pa1 = pa0;
        if (gr < M) {
            const float* ap = A + (size_t)gr * K + k0 + aSeg * 8;
            pa0 = ((const float4*)ap)[0];
            pa1 = ((const float4*)ap)[1];
        }
        const float* bp0 = B + (size_t)(k0 + bRow) * N + gc;
        const float* bp1 = B + (size_t)(k0 + bRow + 8) * N + gc;
        if (nVec) {
            pb0 = *(const float4*)bp0;
            pb1 = *(const float4*)bp1;
        } else {
            pb0.x = (gc + 0 < N) ? bp0[0] : 0.f;
            pb0.y = (gc + 1 < N) ? bp0[1] : 0.f;
            pb0.z = (gc + 2 < N) ? bp0[2] : 0.f;
            pb0.w = (gc + 3 < N) ? bp0[3] : 0.f;
            pb1.x = (gc + 0 < N) ? bp1[0] : 0.f;
            pb1.y = (gc + 1 < N) ? bp1[1] : 0.f;
            pb1.z = (gc + 2 < N) ? bp1[2] : 0.f;
            pb1.w = (gc + 3 < N) ? bp1[3] : 0.f;
        }
    };

    // store fragment-ordered tf32 tiles
    int a_tm = aRow >> 4, a_ln4 = 4 * (aRow & 7), a_i8 = (aRow >> 3) & 1;
    int b_tn = lane >> 1, b_c = bRow & 3, b_hf = (bRow >> 2) & 1;
    int b_g4 = 4 * (lane & 1);
    auto stage = [&](int s) {
        unsigned* stg = sm + s * STG_U32;
        float va[8] = {pa0.x, pa0.y, pa0.z, pa0.w, pa1.x, pa1.y, pa1.z, pa1.w};
        unsigned* aB = stg + (aSeg * 8 + a_tm) * 128;   // *32 lanes *4
        #pragma unroll
        for (int kk = 0; kk < 8; kk++) {
            int cc = kk & 3, hf = kk >> 2;
            aB[(a_ln4 + cc) * 4 + a_i8 + 2 * hf] = f2tf(va[kk]);
        }
        unsigned* bB = stg + 2048;
        float vb[2][4] = {{pb0.x, pb0.y, pb0.z, pb0.w}, {pb1.x, pb1.y, pb1.z, pb1.w}};
        #pragma unroll
        for (int rr = 0; rr < 2; rr++)
            #pragma unroll
            for (int cc = 0; cc < 4; cc++)
                bB[((rr * 16 + b_tn) * 32 + 4 * (b_g4 + cc) + b_c) * 2 + b_hf] =
                    f2tf(vb[rr][cc]);
    };

    fetch(0);
    stage(0);
    __syncthreads();

    int s = 0;
    for (int k0 = 0; k0 < K; k0 += 16) {
        bool hasNext = (k0 + 16) < K;
        if (hasNext) fetch(k0 + 16);   // LDG overlaps MMAs

        const unsigned* stg = sm + s * STG_U32;
        #pragma unroll
        for (int ks = 0; ks < 2; ks++) {
            const uint4* ap = (const uint4*)(stg + ((ks * 8 + 2 * (wid & 3)) * 32 + lane) * 4);
            uint4 a0 = ap[0];
            uint4 a1 = ap[32];
            const uint2* bp = (const uint2*)(stg + 2048 + ((ks * 16 + (wid >> 2) * 8) * 32 + lane) * 2);
            #pragma unroll
            for (int j = 0; j < 8; j++) {
                uint2 b = bp[j * 32];
                asm volatile(
                    "mma.sync.aligned.m16n8k8.row.col.f32.tf32.tf32.f32 "
                    "{%0,%1,%2,%3}, {%4,%5,%6,%7}, {%8,%9}, {%0,%1,%2,%3};"
                    : "+f"(acc[0][j][0]), "+f"(acc[0][j][1]),
                      "+f"(acc[0][j][2]), "+f"(acc[0][j][3])
                    : "r"(a0.x), "r"(a0.y), "r"(a0.z), "r"(a0.w),
                      "r"(b.x), "r"(b.y));
                asm volatile(
                    "mma.sync.aligned.m16n8k8.row.col.f32.tf32.tf32.f32 "
                    "{%0,%1,%2,%3}, {%4,%5,%6,%7}, {%8,%9}, {%0,%1,%2,%3};"
                    : "+f"(acc[1][j][0]), "+f"(acc[1][j][1]),
                      "+f"(acc[1][j][2]), "+f"(acc[1][j][3])
                    : "r"(a1.x), "r"(a1.y), "r"(a1.z), "r"(a1.w),
                      "r"(b.x), "r"(b.y));
            }
        }

        if (hasNext) {
            stage(s ^ 1);
            __syncthreads();
            s ^= 1;
        }
    }

    // epilogue
    int wm = (wid & 3) * 32;
    #pragma unroll
    for (int i = 0; i < 2; i++) {
        int r = row0 + wm + 16 * i + g;
        #pragma unroll
        for (int j = 0; j < 8; j++) {
            int cc = col0 + wn + 8 * j + 2 * c;
            #pragma unroll
            for (int hh = 0; hh < 2; hh++) {
                int rr = r + hh * 8;
                if (rr < M) {
                    float v0 = acc[i][j][hh * 2 + 0];
                    float v1 = acc[i][j][hh * 2 + 1];
                    float* cp = C + (size_t)rr * N + cc;
                    if (nEven) {
                        if (cc + 1 < N) {
                            if (BIAS) { v0 += bias[cc]; v1 += bias[cc + 1]; }
                            if (RELU) { v0 = fmaxf(v0, 0.f); v1 = fmaxf(v1, 0.f); }
                            *(float2*)cp = make_float2(v0, v1);
                        } else if (cc < N) {
                            if (BIAS) v0 += bias[cc];
                            if (RELU) v0 = fmaxf(v0, 0.f);
                            cp[0] = v0;
                        }
                    } else {
                        if (cc < N) {
                            if (BIAS) v0 += bias[cc];
                            if (RELU) v0 = fmaxf(v0, 0.f);
                            cp[0] = v0;
                        }
                        if (cc + 1 < N) {
                            if (BIAS) v1 += bias[cc + 1];
                            if (RELU) v1 = fmaxf(v1, 0.f);
                            cp[1] = v1;
                        }
                    }
                }
            }
        }
    }
}

// ---------------- LayerNorm over D=128 (warp per node) ---------------------
template <int RESID>
__global__ void ln_kernel(const float* __restrict__ X, const float* __restrict__ R,
                          const float* __restrict__ g, const float* __restrict__ b,
                          float* __restrict__ out) {
    int node = blockIdx.x * (blockDim.x >> 5) + (threadIdx.x >> 5);
    if (node >= NN) return;
    int lane = threadIdx.x & 31;
    float4 x = ((const float4*)(X + (size_t)node * DD))[lane];
    if (RESID) {
        float4 r = ((const float4*)(R + (size_t)node * DD))[lane];
        x.x += r.x; x.y += r.y; x.z += r.z; x.w += r.w;
    }
    float s = x.x + x.y + x.z + x.w;
    #pragma unroll
    for (int o = 16; o; o >>= 1) s += __shfl_xor_sync(0xFFFFFFFFu, s, o);
    float mu = s * (1.f / 128.f);
    float dx = x.x - mu, dy = x.y - mu, dz = x.z - mu, dw = x.w - mu;
    float v = dx * dx + dy * dy + dz * dz + dw * dw;
    #pragma unroll
    for (int o = 16; o; o >>= 1) v += __shfl_xor_sync(0xFFFFFFFFu, v, o);
    float rstd = rsqrtf(v * (1.f / 128.f) + 1e-5f);
    float4 gg = ((const float4*)g)[lane];
    float4 bb = ((const float4*)b)[lane];
    float4 o4;
    o4.x = dx * rstd * gg.x + bb.x;
    o4.y = dy * rstd * gg.y + bb.y;
    o4.z = dz * rstd * gg.z + bb.z;
    o4.w = dw * rstd * gg.w + bb.w;
    ((float4*)(out + (size_t)node * DD))[lane] = o4;
}

// ---------------- attention + aggregation (warp per dst node) --------------
__global__ void attn_kernel() {
    int node = blockIdx.x * (blockDim.x >> 5) + (threadIdx.x >> 5);
    if (node >= NN) return;
    int lane = threadIdx.x & 31;
    const float* qkv = g_t;
    float4 qv = ((const float4*)(qkv + (size_t)node * 384))[lane];
    float s = 0.f;
    float4 acc = make_float4(0.f, 0.f, 0.f, 0.f);
    int e0 = g_off[node], e1 = g_off[node + 1];
    int e = e0;
    for (; e + 2 <= e1; e += 2) {
        const float* b0p = qkv + (size_t)g_csr[e] * 384;
        const float* b1p = qkv + (size_t)g_csr[e + 1] * 384;
        float4 k0 = ((const float4*)(b0p + 128))[lane];
        float4 v0 = ((const float4*)(b0p + 256))[lane];
        float4 k1 = ((const float4*)(b1p + 128))[lane];
        float4 v1 = ((const float4*)(b1p + 256))[lane];
        float p0 = qv.x * k0.x + qv.y * k0.y + qv.z * k0.z + qv.w * k0.w;
        float p1 = qv.x * k1.x + qv.y * k1.y + qv.z * k1.z + qv.w * k1.w;
        p0 += __shfl_xor_sync(0xFFFFFFFFu, p0, 1);
        p0 += __shfl_xor_sync(0xFFFFFFFFu, p0, 2);
        p1 += __shfl_xor_sync(0xFFFFFFFFu, p1, 1);
        p1 += __shfl_xor_sync(0xFFFFFFFFu, p1, 2);
        float w0 = __expf(p0 * 0.25f);
        float w1 = __expf(p1 * 0.25f);
        s += w0 + w1;
        acc.x += w0 * v0.x + w1 * v1.x;
        acc.y += w0 * v0.y + w1 * v1.y;
        acc.z += w0 * v0.z + w1 * v1.z;
        acc.w += w0 * v0.w + w1 * v1.w;
    }
    if (e < e1) {
        const float* b0p = qkv + (size_t)g_csr[e] * 384;
        float4 k0 = ((const float4*)(b0p + 128))[lane];
        float4 v0 = ((const float4*)(b0p + 256))[lane];
        float p0 = qv.x * k0.x + qv.y * k0.y + qv.z * k0.z + qv.w * k0.w;
        p0 += __shfl_xor_sync(0xFFFFFFFFu, p0, 1);
        p0 += __shfl_xor_sync(0xFFFFFFFFu, p0, 2);
        float w0 = __expf(p0 * 0.25f);
        s += w0;
        acc.x += w0 * v0.x; acc.y += w0 * v0.y;
        acc.z += w0 * v0.z; acc.w += w0 * v0.w;
    }
    float inv = (s > 0.f) ? 1.f / s : 0.f;
    float4 o = make_float4(acc.x * inv, acc.y * inv, acc.z * inv, acc.w * inv);
    ((float4*)(g_agg + (size_t)node * DD))[lane] = o;
}

// ---------------- host-side launch -----------------------------------------
static inline void run_gemm(int bias, int relu, const float* A, const float* B,
                            const float* bp, float* C, int M, int N, int K) {
    dim3 grid((N + 127) / 128, (M + 127) / 128);
    if (bias && relu)
        tf32gemm_kernel<1, 1><<<grid, 256, GEMM_SMEM_BYTES>>>(A, B, bp, C, M, N, K);
    else if (bias)
        tf32gemm_kernel<1, 0><<<grid, 256, GEMM_SMEM_BYTES>>>(A, B, bp, C, M, N, K);
    else
        tf32gemm_kernel<0, 0><<<grid, 256, GEMM_SMEM_BYTES>>>(A, B, bp, C, M, N, K);
}

extern "C" void kernel_launch(void* const* d_in, const int* in_sizes, int n_in,
                              void* d_out, int out_size) {
    const float* X        = (const float*)d_in[0];
    const int*   ei       = (const int*)d_in[1];
    const float* emb_w    = (const float*)d_in[2];
    const float* emb_b    = (const float*)d_in[3];
    const float* emb_ln_g = (const float*)d_in[4];
    const float* emb_ln_b = (const float*)d_in[5];
    const float* Wq       = (const float*)d_in[6];
    const float* Wk       = (const float*)d_in[7];
    const float* Wv       = (const float*)d_in[8];
    const float* Wo       = (const float*)d_in[9];
    const float* ln_g     = (const float*)d_in[10];
    const float* ln_b     = (const float*)d_in[11];
    const float* f1_w     = (const float*)d_in[12];
    const float* f1_b     = (const float*)d_in[13];
    const float* f2_w     = (const float*)d_in[14];
    const float* f2_b     = (const float*)d_in[15];
    const float* f3_w     = (const float*)d_in[16];
    const float* f3_b     = (const float*)d_in[17];
    float* out = (float*)d_out;

    const int* src = ei;
    const int* dst = ei + EE;

    cudaFuncSetAttribute(tf32gemm_kernel<1, 1>,
                         cudaFuncAttributeMaxDynamicSharedMemorySize, GEMM_SMEM_BYTES);
    cudaFuncSetAttribute(tf32gemm_kernel<1, 0>,
                         cudaFuncAttributeMaxDynamicSharedMemorySize, GEMM_SMEM_BYTES);
    cudaFuncSetAttribute(tf32gemm_kernel<0, 0>,
                         cudaFuncAttributeMaxDynamicSharedMemorySize, GEMM_SMEM_BYTES);

    float *p_h, *p_agg, *p_t, *p_t2, *p_wqkv;
    cudaGetSymbolAddress((void**)&p_h,    g_h);
    cudaGetSymbolAddress((void**)&p_agg,  g_agg);
    cudaGetSymbolAddress((void**)&p_t,    g_t);
    cudaGetSymbolAddress((void**)&p_t2,   g_t2);
    cudaGetSymbolAddress((void**)&p_wqkv, g_wqkv);

    // ---- CSR build (by dst) + weight packing ----
    zero_deg_kernel<<<(NN + 255) / 256, 256>>>();
    count_deg_kernel<<<(EE + 255) / 256, 256>>>(dst);
    scan_kernel<<<1, 1024>>>();
    scatter_kernel<<<(EE + 255) / 256, 256>>>(src, dst);
    pack_qkv_kernel<<<(LL * DD * DD + 255) / 256, 256>>>(Wq, Wk, Wv);

    // ---- embedding: relu(X @ emb_w + b) -> LN -> h ----
    run_gemm(1, 1, X, emb_w, emb_b, p_t2, NN, DD, DIN);
    ln_kernel<0><<<(NN + 7) / 8, 256>>>(p_t2, nullptr, emb_ln_g, emb_ln_b, p_h);

    // ---- layers ----
    for (int l = 0; l < LL; l++) {
        const float* wo = Wo + (size_t)l * DD * DD;
        run_gemm(0, 0, p_h, p_wqkv + (size_t)l * DD * 384, nullptr, p_t, NN, 384, DD);
        attn_kernel<<<(NN + 7) / 8, 256>>>();
        run_gemm(0, 0, p_agg, wo, nullptr, p_t2, NN, DD, DD);
        ln_kernel<1><<<(NN + 7) / 8, 256>>>(p_t2, p_h, ln_g + l * DD, ln_b + l * DD, p_h);
    }

    // ---- MLP head ----
    run_gemm(1, 1, p_h,  f1_w, f1_b, p_t,  NN, 512, DD);
    run_gemm(1, 1, p_t,  f2_w, f2_b, p_t2, NN, 512, 512);
    run_gemm(1, 0, p_t2, f3_w, f3_b, out,  NN, NCC, 512);
}

// round 11
// speedup vs baseline: 2.1240x; 2.1240x over previous
#include <cuda_runtime.h>
#include <math.h>
#include <math_constants.h>

#define NN 50000
#define EE 640000
#define DIN 256
#define DD 128
#define HH 8
#define NCC 47
#define LL 3

// ---------------- scratch (static device allocations; no runtime alloc) ----
__device__ float g_h[NN * DD];
__device__ float g_agg[NN * DD];
__device__ float g_t[NN * 512];       // qkv [N,384] per layer; also ff1 [N,512]
__device__ float g_t2[NN * 512];      // agg@Wo [N,128]; ff2 [N,512]
__device__ float g_wqkv[LL * DD * 384];
__device__ int   g_deg[NN];
__device__ int   g_off[NN + 1];
__device__ int   g_cur[NN];
__device__ int   g_csr[EE];

// ---------------- CSR build ------------------------------------------------
__global__ void zero_deg_kernel() {
    int i = blockIdx.x * blockDim.x + threadIdx.x;
    if (i < NN) g_deg[i] = 0;
}

__global__ void count_deg_kernel(const int* __restrict__ dst) {
    int e = blockIdx.x * blockDim.x + threadIdx.x;
    if (e < EE) atomicAdd(&g_deg[dst[e]], 1);
}

__global__ void scan_kernel() {
    __shared__ int wsum[32];
    __shared__ int carry_s;
    int t = threadIdx.x, lane = t & 31, wid = t >> 5;
    if (t == 0) carry_s = 0;
    __syncthreads();
    for (int base = 0; base < NN; base += 1024) {
        int i = base + t;
        int val = (i < NN) ? g_deg[i] : 0;
        int incl = val;
        #pragma unroll
        for (int o = 1; o < 32; o <<= 1) {
            int x = __shfl_up_sync(0xFFFFFFFFu, incl, o);
            if (lane >= o) incl += x;
        }
        if (lane == 31) wsum[wid] = incl;
        __syncthreads();
        if (wid == 0) {
            int wv = wsum[lane];
            int wincl = wv;
            #pragma unroll
            for (int o = 1; o < 32; o <<= 1) {
                int x = __shfl_up_sync(0xFFFFFFFFu, wincl, o);
                if (lane >= o) wincl += x;
            }
            wsum[lane] = wincl - wv;
        }
        __syncthreads();
        int carry = carry_s;
        int excl = carry + wsum[wid] + incl - val;
        if (i < NN) { g_off[i] = excl; g_cur[i] = excl; }
        __syncthreads();
        if (t == 1023) carry_s = carry + wsum[31] + incl;
        __syncthreads();
    }
    if (threadIdx.x == 0) g_off[NN] = carry_s;
}

__global__ void scatter_kernel(const int* __restrict__ src, const int* __restrict__ dst) {
    int e = blockIdx.x * blockDim.x + threadIdx.x;
    if (e < EE) {
        int d = dst[e];
        int pos = atomicAdd(&g_cur[d], 1);
        g_csr[pos] = src[e];
    }
}

// ---------------- pack Wq|Wk|Wv -> [L][128][384] ---------------------------
__global__ void pack_qkv_kernel(const float* __restrict__ Wq,
                                const float* __restrict__ Wk,
                                const float* __restrict__ Wv) {
    int i = blockIdx.x * blockDim.x + threadIdx.x;
    if (i < LL * DD * DD) {
        int l = i / (DD * DD);
        int r = (i / DD) % DD;
        int c = i % DD;
        size_t o = ((size_t)l * DD + r) * 384;
        g_wqkv[o + c]       = Wq[i];
        g_wqkv[o + 128 + c] = Wk[i];
        g_wqkv[o + 256 + c] = Wv[i];
    }
}

// ---------------- TF32 tensor-core GEMM (double-buffered, 2 blocks/SM) -----
// BM=BN=128, BK=16, 256 threads, 8 warps 4(M)x2(N), 32x64 warp tile.
// Padded [16][136] smem layout (proven conflict-free both directions).
// __launch_bounds__(256,2) caps regs at 128 -> 2 resident blocks per SM so
// one block's MMAs cover the other's barrier/staging bubbles.
__device__ __forceinline__ unsigned f2tf(float f) {
    unsigned u;
    asm("cvt.rna.tf32.f32 %0, %1;" : "=r"(u) : "f"(f));
    return u;
}

#define GEMM_SMEM_BYTES (2 * 2 * 16 * 136 * 4)

template <int BIAS, int RELU>
__global__ void __launch_bounds__(256, 2)
tf32gemm_kernel(const float* __restrict__ A, const float* __restrict__ B,
                const float* __restrict__ bias, float* __restrict__ C,
                int M, int N, int K) {
    extern __shared__ unsigned sm[];
    unsigned (*As)[16][136] = (unsigned (*)[16][136])sm;
    unsigned (*Bs)[16][136] = (unsigned (*)[16][136])(sm + 2 * 16 * 136);

    int tid = threadIdx.x, lane = tid & 31, wid = tid >> 5;
    int row0 = blockIdx.y * 128, col0 = blockIdx.x * 128;
    int wm = (wid & 3) * 32, wn = (wid >> 2) * 64;
    int g = lane >> 2, c = lane & 3;

    int aRow = tid >> 1, aSeg = tid & 1;
    int bRow = tid >> 5;
    int gr = row0 + aRow;
    int gc = col0 + lane * 4;

    const bool nVec = ((N & 127) == 0);
    const bool nEven = ((N & 1) == 0);

    float acc[2][8][4];
    #pragma unroll
    for (int i = 0; i < 2; i++)
        #pragma unroll
        for (int j = 0; j < 8; j++)
            #pragma unroll
            for (int r = 0; r < 4; r++) acc[i][j][r] = 0.f;

    float4 pa0, pa1, pb0, pb1;

    auto fetch = [&](int k0) {
        pa0 = make_float4(0.f, 0.f, 0.f, 0.f); pa1 = pa0;
        if (gr < M) {
            const float* ap = A + (size_t)gr * K + k0 + aSeg * 8;
            pa0 = ((const float4*)ap)[0];
            pa1 = ((const float4*)ap)[1];
        }
        const float* bp0 = B + (size_t)(k0 + bRow) * N + gc;
        const float* bp1 = B + (size_t)(k0 + bRow + 8) * N + gc;
        if (nVec) {
            pb0 = *(const float4*)bp0;
            pb1 = *(const float4*)bp1;
        } else {
            pb0.x = (gc + 0 < N) ? bp0[0] : 0.f;
            pb0.y = (gc + 1 < N) ? bp0[1] : 0.f;
            pb0.z = (gc + 2 < N) ? bp0[2] : 0.f;
            pb0.w = (gc + 3 < N) ? bp0[3] : 0.f;
            pb1.x = (gc + 0 < N) ? bp1[0] : 0.f;
            pb1.y = (gc + 1 < N) ? bp1[1] : 0.f;
            pb1.z = (gc + 2 < N) ? bp1[2] : 0.f;
            pb1.w = (gc + 3 < N) ? bp1[3] : 0.f;
        }
    };
    auto stage = [&](int s) {
        int kb = aSeg * 8;
        As[s][kb + 0][aRow] = f2tf(pa0.x);
        As[s][kb + 1][aRow] = f2tf(pa0.y);
        As[s][kb + 2][aRow] = f2tf(pa0.z);
        As[s][kb + 3][aRow] = f2tf(pa0.w);
        As[s][kb + 4][aRow] = f2tf(pa1.x);
        As[s][kb + 5][aRow] = f2tf(pa1.y);
        As[s][kb + 6][aRow] = f2tf(pa1.z);
        As[s][kb + 7][aRow] = f2tf(pa1.w);
        Bs[s][bRow][lane * 4 + 0] = f2tf(pb0.x);
        Bs[s][bRow][lane * 4 + 1] = f2tf(pb0.y);
        Bs[s][bRow][lane * 4 + 2] = f2tf(pb0.z);
        Bs[s][bRow][lane * 4 + 3] = f2tf(pb0.w);
        Bs[s][bRow + 8][lane * 4 + 0] = f2tf(pb1.x);
        Bs[s][bRow + 8][lane * 4 + 1] = f2tf(pb1.y);
        Bs[s][bRow + 8][lane * 4 + 2] = f2tf(pb1.z);
        Bs[s][bRow + 8][lane * 4 + 3] = f2tf(pb1.w);
    };

    fetch(0);
    stage(0);
    __syncthreads();

    int s = 0;
    for (int k0 = 0; k0 < K; k0 += 16) {
        bool hasNext = (k0 + 16) < K;
        if (hasNext) fetch(k0 + 16);

        #pragma unroll
        for (int ks = 0; ks < 2; ks++) {
            int kb = ks * 8;
            unsigned a[2][4];
            #pragma unroll
            for (int i = 0; i < 2; i++) {
                int m = wm + 16 * i + g;
                a[i][0] = As[s][kb + c][m];
                a[i][1] = As[s][kb + c][m + 8];
                a[i][2] = As[s][kb + c + 4][m];
                a[i][3] = As[s][kb + c + 4][m + 8];
            }
            #pragma unroll
            for (int j = 0; j < 8; j++) {
                unsigned b0 = Bs[s][kb + c][wn + 8 * j + g];
                unsigned b1 = Bs[s][kb + c + 4][wn + 8 * j + g];
                #pragma unroll
                for (int i = 0; i < 2; i++) {
                    asm volatile(
                        "mma.sync.aligned.m16n8k8.row.col.f32.tf32.tf32.f32 "
                        "{%0,%1,%2,%3}, {%4,%5,%6,%7}, {%8,%9}, {%0,%1,%2,%3};"
                        : "+f"(acc[i][j][0]), "+f"(acc[i][j][1]),
                          "+f"(acc[i][j][2]), "+f"(acc[i][j][3])
                        : "r"(a[i][0]), "r"(a[i][1]), "r"(a[i][2]), "r"(a[i][3]),
                          "r"(b0), "r"(b1));
                }
            }
        }

        if (hasNext) {
            stage(s ^ 1);
            __syncthreads();
            s ^= 1;
        }
    }

    // epilogue
    #pragma unroll
    for (int i = 0; i < 2; i++) {
        int r = row0 + wm + 16 * i + g;
        #pragma unroll
        for (int j = 0; j < 8; j++) {
            int cc = col0 + wn + 8 * j + 2 * c;
            #pragma unroll
            for (int hh = 0; hh < 2; hh++) {
                int rr = r + hh * 8;
                if (rr < M) {
                    float v0 = acc[i][j][hh * 2 + 0];
                    float v1 = acc[i][j][hh * 2 + 1];
                    float* cp = C + (size_t)rr * N + cc;
                    if (nEven) {
                        if (cc + 1 < N) {
                            if (BIAS) { v0 += bias[cc]; v1 += bias[cc + 1]; }
                            if (RELU) { v0 = fmaxf(v0, 0.f); v1 = fmaxf(v1, 0.f); }
                            *(float2*)cp = make_float2(v0, v1);
                        } else if (cc < N) {
                            if (BIAS) v0 += bias[cc];
                            if (RELU) v0 = fmaxf(v0, 0.f);
                            cp[0] = v0;
                        }
                    } else {
                        if (cc < N) {
                            if (BIAS) v0 += bias[cc];
                            if (RELU) v0 = fmaxf(v0, 0.f);
                            cp[0] = v0;
                        }
                        if (cc + 1 < N) {
                            if (BIAS) v1 += bias[cc + 1];
                            if (RELU) v1 = fmaxf(v1, 0.f);
                            cp[1] = v1;
                        }
                    }
                }
            }
        }
    }
}

// ---------------- LayerNorm over D=128 (warp per node) ---------------------
template <int RESID>
__global__ void ln_kernel(const float* __restrict__ X, const float* __restrict__ R,
                          const float* __restrict__ g, const float* __restrict__ b,
                          float* __restrict__ out) {
    int node = blockIdx.x * (blockDim.x >> 5) + (threadIdx.x >> 5);
    if (node >= NN) return;
    int lane = threadIdx.x & 31;
    float4 x = ((const float4*)(X + (size_t)node * DD))[lane];
    if (RESID) {
        float4 r = ((const float4*)(R + (size_t)node * DD))[lane];
        x.x += r.x; x.y += r.y; x.z += r.z; x.w += r.w;
    }
    float s = x.x + x.y + x.z + x.w;
    #pragma unroll
    for (int o = 16; o; o >>= 1) s += __shfl_xor_sync(0xFFFFFFFFu, s, o);
    float mu = s * (1.f / 128.f);
    float dx = x.x - mu, dy = x.y - mu, dz = x.z - mu, dw = x.w - mu;
    float v = dx * dx + dy * dy + dz * dz + dw * dw;
    #pragma unroll
    for (int o = 16; o; o >>= 1) v += __shfl_xor_sync(0xFFFFFFFFu, v, o);
    float rstd = rsqrtf(v * (1.f / 128.f) + 1e-5f);
    float4 gg = ((const float4*)g)[lane];
    float4 bb = ((const float4*)b)[lane];
    float4 o4;
    o4.x = dx * rstd * gg.x + bb.x;
    o4.y = dy * rstd * gg.y + bb.y;
    o4.z = dz * rstd * gg.z + bb.z;
    o4.w = dw * rstd * gg.w + bb.w;
    ((float4*)(out + (size_t)node * DD))[lane] = o4;
}

// ---------------- attention + aggregation (warp per dst node) --------------
__global__ void attn_kernel() {
    int node = blockIdx.x * (blockDim.x >> 5) + (threadIdx.x >> 5);
    if (node >= NN) return;
    int lane = threadIdx.x & 31;
    const float* qkv = g_t;
    float4 qv = ((const float4*)(qkv + (size_t)node * 384))[lane];
    float s = 0.f;
    float4 acc = make_float4(0.f, 0.f, 0.f, 0.f);
    int e0 = g_off[node], e1 = g_off[node + 1];
    int e = e0;
    for (; e + 2 <= e1; e += 2) {
        const float* b0p = qkv + (size_t)g_csr[e] * 384;
        const float* b1p = qkv + (size_t)g_csr[e + 1] * 384;
        float4 k0 = ((const float4*)(b0p + 128))[lane];
        float4 v0 = ((const float4*)(b0p + 256))[lane];
        float4 k1 = ((const float4*)(b1p + 128))[lane];
        float4 v1 = ((const float4*)(b1p + 256))[lane];
        float p0 = qv.x * k0.x + qv.y * k0.y + qv.z * k0.z + qv.w * k0.w;
        float p1 = qv.x * k1.x + qv.y * k1.y + qv.z * k1.z + qv.w * k1.w;
        p0 += __shfl_xor_sync(0xFFFFFFFFu, p0, 1);
        p0 += __shfl_xor_sync(0xFFFFFFFFu, p0, 2);
        p1 += __shfl_xor_sync(0xFFFFFFFFu, p1, 1);
        p1 += __shfl_xor_sync(0xFFFFFFFFu, p1, 2);
        float w0 = __expf(p0 * 0.25f);
        float w1 = __expf(p1 * 0.25f);
        s += w0 + w1;
        acc.x += w0 * v0.x + w1 * v1.x;
        acc.y += w0 * v0.y + w1 * v1.y;
        acc.z += w0 * v0.z + w1 * v1.z;
        acc.w += w0 * v0.w + w1 * v1.w;
    }
    if (e < e1) {
        const float* b0p = qkv + (size_t)g_csr[e] * 384;
        float4 k0 = ((const float4*)(b0p + 128))[lane];
        float4 v0 = ((const float4*)(b0p + 256))[lane];
        float p0 = qv.x * k0.x + qv.y * k0.y + qv.z * k0.z + qv.w * k0.w;
        p0 += __shfl_xor_sync(0xFFFFFFFFu, p0, 1);
        p0 += __shfl_xor_sync(0xFFFFFFFFu, p0, 2);
        float w0 = __expf(p0 * 0.25f);
        s += w0;
        acc.x += w0 * v0.x; acc.y += w0 * v0.y;
        acc.z += w0 * v0.z; acc.w += w0 * v0.w;
    }
    float inv = (s > 0.f) ? 1.f / s : 0.f;
    float4 o = make_float4(acc.x * inv, acc.y * inv, acc.z * inv, acc.w * inv);
    ((float4*)(g_agg + (size_t)node * DD))[lane] = o;
}

// ---------------- host-side launch -----------------------------------------
static inline void run_gemm(int bias, int relu, const float* A, const float* B,
                            const float* bp, float* C, int M, int N, int K) {
    dim3 grid((N + 127) / 128, (M + 127) / 128);
    if (bias && relu)
        tf32gemm_kernel<1, 1><<<grid, 256, GEMM_SMEM_BYTES>>>(A, B, bp, C, M, N, K);
    else if (bias)
        tf32gemm_kernel<1, 0><<<grid, 256, GEMM_SMEM_BYTES>>>(A, B, bp, C, M, N, K);
    else
        tf32gemm_kernel<0, 0><<<grid, 256, GEMM_SMEM_BYTES>>>(A, B, bp, C, M, N, K);
}

extern "C" void kernel_launch(void* const* d_in, const int* in_sizes, int n_in,
                              void* d_out, int out_size) {
    const float* X        = (const float*)d_in[0];
    const int*   ei       = (const int*)d_in[1];
    const float* emb_w    = (const float*)d_in[2];
    const float* emb_b    = (const float*)d_in[3];
    const float* emb_ln_g = (const float*)d_in[4];
    const float* emb_ln_b = (const float*)d_in[5];
    const float* Wq       = (const float*)d_in[6];
    const float* Wk       = (const float*)d_in[7];
    const float* Wv       = (const float*)d_in[8];
    const float* Wo       = (const float*)d_in[9];
    const float* ln_g     = (const float*)d_in[10];
    const float* ln_b     = (const float*)d_in[11];
    const float* f1_w     = (const float*)d_in[12];
    const float* f1_b     = (const float*)d_in[13];
    const float* f2_w     = (const float*)d_in[14];
    const float* f2_b     = (const float*)d_in[15];
    const float* f3_w     = (const float*)d_in[16];
    const float* f3_b     = (const float*)d_in[17];
    float* out = (float*)d_out;

    const int* src = ei;
    const int* dst = ei + EE;

    cudaFuncSetAttribute(tf32gemm_kernel<1, 1>,
                         cudaFuncAttributeMaxDynamicSharedMemorySize, GEMM_SMEM_BYTES);
    cudaFuncSetAttribute(tf32gemm_kernel<1, 0>,
                         cudaFuncAttributeMaxDynamicSharedMemorySize, GEMM_SMEM_BYTES);
    cudaFuncSetAttribute(tf32gemm_kernel<0, 0>,
                         cudaFuncAttributeMaxDynamicSharedMemorySize, GEMM_SMEM_BYTES);

    float *p_h, *p_agg, *p_t, *p_t2, *p_wqkv;
    cudaGetSymbolAddress((void**)&p_h,    g_h);
    cudaGetSymbolAddress((void**)&p_agg,  g_agg);
    cudaGetSymbolAddress((void**)&p_t,    g_t);
    cudaGetSymbolAddress((void**)&p_t2,   g_t2);
    cudaGetSymbolAddress((void**)&p_wqkv, g_wqkv);

    // ---- CSR build (by dst) + weight packing ----
    zero_deg_kernel<<<(NN + 255) / 256, 256>>>();
    count_deg_kernel<<<(EE + 255) / 256, 256>>>(dst);
    scan_kernel<<<1, 1024>>>();
    scatter_kernel<<<(EE + 255) / 256, 256>>>(src, dst);
    pack_qkv_kernel<<<(LL * DD * DD + 255) / 256, 256>>>(Wq, Wk, Wv);

    // ---- embedding: relu(X @ emb_w + b) -> LN -> h ----
    run_gemm(1, 1, X, emb_w, emb_b, p_t2, NN, DD, DIN);
    ln_kernel<0><<<(NN + 7) / 8, 256>>>(p_t2, nullptr, emb_ln_g, emb_ln_b, p_h);

    // ---- layers ----
    for (int l = 0; l < LL; l++) {
        const float* wo = Wo + (size_t)l * DD * DD;
        run_gemm(0, 0, p_h, p_wqkv + (size_t)l * DD * 384, nullptr, p_t, NN, 384, DD);
        attn_kernel<<<(NN + 7) / 8, 256>>>();
        run_gemm(0, 0, p_agg, wo, nullptr, p_t2, NN, DD, DD);
        ln_kernel<1><<<(NN + 7) / 8, 256>>>(p_t2, p_h, ln_g + l * DD, ln_b + l * DD, p_h);
    }

    // ---- MLP head ----
    run_gemm(1, 1, p_h,  f1_w, f1_b, p_t,  NN, 512, DD);
    run_gemm(1, 1, p_t,  f2_w, f2_b, p_t2, NN, 512, 512);
    run_gemm(1, 0, p_t2, f3_w, f3_b, out,  NN, NCC, 512);
}

// round 12
// speedup vs baseline: 2.1473x; 1.0110x over previous
#include <cuda_runtime.h>
#include <math.h>
#include <math_constants.h>

#define NN 50000
#define EE 640000
#define DIN 256
#define DD 128
#define HH 8
#define NCC 47
#define LL 3

// ---------------- scratch (static device allocations; no runtime alloc) ----
__device__ float g_h[NN * DD];
__device__ float g_agg[NN * DD];
__device__ float g_t[NN * 512];       // qkv [N,384] per layer; also ff1 [N,512]
__device__ float g_t2[NN * 512];      // ff2 [N,512]
__device__ float g_wqkv[LL * DD * 384];
__device__ int   g_deg[NN];
__device__ int   g_off[NN + 1];
__device__ int   g_cur[NN];
__device__ int   g_csr[EE];

// ---------------- CSR build ------------------------------------------------
__global__ void zero_deg_kernel() {
    int i = blockIdx.x * blockDim.x + threadIdx.x;
    if (i < NN) g_deg[i] = 0;
}

__global__ void count_deg_kernel(const int* __restrict__ dst) {
    int e = blockIdx.x * blockDim.x + threadIdx.x;
    if (e < EE) atomicAdd(&g_deg[dst[e]], 1);
}

__global__ void scan_kernel() {
    __shared__ int wsum[32];
    __shared__ int carry_s;
    int t = threadIdx.x, lane = t & 31, wid = t >> 5;
    if (t == 0) carry_s = 0;
    __syncthreads();
    for (int base = 0; base < NN; base += 1024) {
        int i = base + t;
        int val = (i < NN) ? g_deg[i] : 0;
        int incl = val;
        #pragma unroll
        for (int o = 1; o < 32; o <<= 1) {
            int x = __shfl_up_sync(0xFFFFFFFFu, incl, o);
            if (lane >= o) incl += x;
        }
        if (lane == 31) wsum[wid] = incl;
        __syncthreads();
        if (wid == 0) {
            int wv = wsum[lane];
            int wincl = wv;
            #pragma unroll
            for (int o = 1; o < 32; o <<= 1) {
                int x = __shfl_up_sync(0xFFFFFFFFu, wincl, o);
                if (lane >= o) wincl += x;
            }
            wsum[lane] = wincl - wv;
        }
        __syncthreads();
        int carry = carry_s;
        int excl = carry + wsum[wid] + incl - val;
        if (i < NN) { g_off[i] = excl; g_cur[i] = excl; }
        __syncthreads();
        if (t == 1023) carry_s = carry + wsum[31] + incl;
        __syncthreads();
    }
    if (threadIdx.x == 0) g_off[NN] = carry_s;
}

__global__ void scatter_kernel(const int* __restrict__ src, const int* __restrict__ dst) {
    int e = blockIdx.x * blockDim.x + threadIdx.x;
    if (e < EE) {
        int d = dst[e];
        int pos = atomicAdd(&g_cur[d], 1);
        g_csr[pos] = src[e];
    }
}

// ---------------- pack Wq|Wk|Wv -> [L][128][384] ---------------------------
__global__ void pack_qkv_kernel(const float* __restrict__ Wq,
                                const float* __restrict__ Wk,
                                const float* __restrict__ Wv) {
    int i = blockIdx.x * blockDim.x + threadIdx.x;
    if (i < LL * DD * DD) {
        int l = i / (DD * DD);
        int r = (i / DD) % DD;
        int c = i % DD;
        size_t o = ((size_t)l * DD + r) * 384;
        g_wqkv[o + c]       = Wq[i];
        g_wqkv[o + 128 + c] = Wk[i];
        g_wqkv[o + 256 + c] = Wv[i];
    }
}

// ---------------- TF32 tensor-core GEMM (double-buffered, 2 blocks/SM) -----
// BM=BN=128, BK=16, 256 threads, 8 warps 4(M)x2(N), 32x64 warp tile.
// LN=1 (requires N==128, grid.x==1): LayerNorm fused into the epilogue with
// optional residual add — block covers full rows, 2-warp smem reduction.
__device__ __forceinline__ unsigned f2tf(float f) {
    unsigned u;
    asm("cvt.rna.tf32.f32 %0, %1;" : "=r"(u) : "f"(f));
    return u;
}

#define GEMM_SMEM_BYTES (2 * 2 * 16 * 136 * 4)

template <int BIAS, int RELU, int LN>
__global__ void __launch_bounds__(256, 2)
tf32gemm_kernel(const float* __restrict__ A, const float* __restrict__ B,
                const float* __restrict__ bias, float* __restrict__ C,
                int M, int N, int K,
                const float* __restrict__ resid,
                const float* __restrict__ lngam,
                const float* __restrict__ lnbet) {
    extern __shared__ unsigned sm[];
    unsigned (*As)[16][136] = (unsigned (*)[16][136])sm;
    unsigned (*Bs)[16][136] = (unsigned (*)[16][136])(sm + 2 * 16 * 136);

    int tid = threadIdx.x, lane = tid & 31, wid = tid >> 5;
    int row0 = blockIdx.y * 128, col0 = blockIdx.x * 128;
    int wm = (wid & 3) * 32, wn = (wid >> 2) * 64;
    int g = lane >> 2, c = lane & 3;

    int aRow = tid >> 1, aSeg = tid & 1;
    int bRow = tid >> 5;
    int gr = row0 + aRow;
    int gc = col0 + lane * 4;

    const bool nVec = ((N & 127) == 0);
    const bool nEven = ((N & 1) == 0);

    float acc[2][8][4];
    #pragma unroll
    for (int i = 0; i < 2; i++)
        #pragma unroll
        for (int j = 0; j < 8; j++)
            #pragma unroll
            for (int r = 0; r < 4; r++) acc[i][j][r] = 0.f;

    float4 pa0, pa1, pb0, pb1;

    auto fetch = [&](int k0) {
        pa0 = make_float4(0.f, 0.f, 0.f, 0.f); pa1 = pa0;
        if (gr < M) {
            const float* ap = A + (size_t)gr * K + k0 + aSeg * 8;
            pa0 = ((const float4*)ap)[0];
            pa1 = ((const float4*)ap)[1];
        }
        const float* bp0 = B + (size_t)(k0 + bRow) * N + gc;
        const float* bp1 = B + (size_t)(k0 + bRow + 8) * N + gc;
        if (nVec) {
            pb0 = *(const float4*)bp0;
            pb1 = *(const float4*)bp1;
        } else {
            pb0.x = (gc + 0 < N) ? bp0[0] : 0.f;
            pb0.y = (gc + 1 < N) ? bp0[1] : 0.f;
            pb0.z = (gc + 2 < N) ? bp0[2] : 0.f;
            pb0.w = (gc + 3 < N) ? bp0[3] : 0.f;
            pb1.x = (gc + 0 < N) ? bp1[0] : 0.f;
            pb1.y = (gc + 1 < N) ? bp1[1] : 0.f;
            pb1.z = (gc + 2 < N) ? bp1[2] : 0.f;
            pb1.w = (gc + 3 < N) ? bp1[3] : 0.f;
        }
    };
    auto stage = [&](int s) {
        int kb = aSeg * 8;
        As[s][kb + 0][aRow] = f2tf(pa0.x);
        As[s][kb + 1][aRow] = f2tf(pa0.y);
        As[s][kb + 2][aRow] = f2tf(pa0.z);
        As[s][kb + 3][aRow] = f2tf(pa0.w);
        As[s][kb + 4][aRow] = f2tf(pa1.x);
        As[s][kb + 5][aRow] = f2tf(pa1.y);
        As[s][kb + 6][aRow] = f2tf(pa1.z);
        As[s][kb + 7][aRow] = f2tf(pa1.w);
        Bs[s][bRow][lane * 4 + 0] = f2tf(pb0.x);
        Bs[s][bRow][lane * 4 + 1] = f2tf(pb0.y);
        Bs[s][bRow][lane * 4 + 2] = f2tf(pb0.z);
        Bs[s][bRow][lane * 4 + 3] = f2tf(pb0.w);
        Bs[s][bRow + 8][lane * 4 + 0] = f2tf(pb1.x);
        Bs[s][bRow + 8][lane * 4 + 1] = f2tf(pb1.y);
        Bs[s][bRow + 8][lane * 4 + 2] = f2tf(pb1.z);
        Bs[s][bRow + 8][lane * 4 + 3] = f2tf(pb1.w);
    };

    fetch(0);
    stage(0);
    __syncthreads();

    int s = 0;
    for (int k0 = 0; k0 < K; k0 += 16) {
        bool hasNext = (k0 + 16) < K;
        if (hasNext) fetch(k0 + 16);

        #pragma unroll
        for (int ks = 0; ks < 2; ks++) {
            int kb = ks * 8;
            unsigned a[2][4];
            #pragma unroll
            for (int i = 0; i < 2; i++) {
                int m = wm + 16 * i + g;
                a[i][0] = As[s][kb + c][m];
                a[i][1] = As[s][kb + c][m + 8];
                a[i][2] = As[s][kb + c + 4][m];
                a[i][3] = As[s][kb + c + 4][m + 8];
            }
            #pragma unroll
            for (int j = 0; j < 8; j++) {
                unsigned b0 = Bs[s][kb + c][wn + 8 * j + g];
                unsigned b1 = Bs[s][kb + c + 4][wn + 8 * j + g];
                #pragma unroll
                for (int i = 0; i < 2; i++) {
                    asm volatile(
                        "mma.sync.aligned.m16n8k8.row.col.f32.tf32.tf32.f32 "
                        "{%0,%1,%2,%3}, {%4,%5,%6,%7}, {%8,%9}, {%0,%1,%2,%3};"
                        : "+f"(acc[i][j][0]), "+f"(acc[i][j][1]),
                          "+f"(acc[i][j][2]), "+f"(acc[i][j][3])
                        : "r"(a[i][0]), "r"(a[i][1]), "r"(a[i][2]), "r"(a[i][3]),
                          "r"(b0), "r"(b1));
                }
            }
        }

        if (hasNext) {
            stage(s ^ 1);
            __syncthreads();
            s ^= 1;
        }
    }

    if (LN) {
        // ---- fused LayerNorm epilogue (N==128, one block per 128 rows) ----
        __syncthreads();                       // tile smem now reusable
        float* rsum = (float*)sm;              // [2][128]
        float* rsq  = (float*)sm + 256;        // [2][128]
        int half = wn >> 6;                    // 0 or 1
        #pragma unroll
        for (int i = 0; i < 2; i++) {
            #pragma unroll
            for (int hh = 0; hh < 2; hh++) {
                int lr = wm + 16 * i + 8 * hh + g;
                int rr = row0 + lr;
                float s16 = 0.f, q16 = 0.f;
                #pragma unroll
                for (int j = 0; j < 8; j++) {
                    int cc = wn + 8 * j + 2 * c;
                    float v0 = acc[i][j][2 * hh + 0];
                    float v1 = acc[i][j][2 * hh + 1];
                    if (BIAS) { v0 += bias[cc]; v1 += bias[cc + 1]; }
                    if (RELU) { v0 = fmaxf(v0, 0.f); v1 = fmaxf(v1, 0.f); }
                    if (resid != nullptr && rr < M) {
                        float2 rv = *(const float2*)(resid + (size_t)rr * 128 + cc);
                        v0 += rv.x; v1 += rv.y;
                    }
                    acc[i][j][2 * hh + 0] = v0;
                    acc[i][j][2 * hh + 1] = v1;
                    s16 += v0 + v1;
                    q16 += v0 * v0 + v1 * v1;
                }
                s16 += __shfl_xor_sync(0xFFFFFFFFu, s16, 1);
                s16 += __shfl_xor_sync(0xFFFFFFFFu, s16, 2);
                q16 += __shfl_xor_sync(0xFFFFFFFFu, q16, 1);
                q16 += __shfl_xor_sync(0xFFFFFFFFu, q16, 2);
                if (c == 0) {
                    rsum[half * 128 + lr] = s16;
                    rsq [half * 128 + lr] = q16;
                }
            }
        }
        __syncthreads();
        #pragma unroll
        for (int i = 0; i < 2; i++) {
            #pragma unroll
            for (int hh = 0; hh < 2; hh++) {
                int lr = wm + 16 * i + 8 * hh + g;
                int rr = row0 + lr;
                if (rr >= M) continue;
                float tot = rsum[lr] + rsum[128 + lr];
                float tq  = rsq[lr]  + rsq[128 + lr];
                float mu  = tot * (1.f / 128.f);
                float var = tq * (1.f / 128.f) - mu * mu;
                float rstd = rsqrtf(var + 1e-5f);
                #pragma unroll
                for (int j = 0; j < 8; j++) {
                    int cc = wn + 8 * j + 2 * c;
                    float2 gg = *(const float2*)(lngam + cc);
                    float2 bb = *(const float2*)(lnbet + cc);
                    float y0 = (acc[i][j][2 * hh + 0] - mu) * rstd * gg.x + bb.x;
                    float y1 = (acc[i][j][2 * hh + 1] - mu) * rstd * gg.y + bb.y;
                    *(float2*)(C + (size_t)rr * 128 + cc) = make_float2(y0, y1);
                }
            }
        }
        return;
    }

    // ---- plain epilogue ----
    #pragma unroll
    for (int i = 0; i < 2; i++) {
        int r = row0 + wm + 16 * i + g;
        #pragma unroll
        for (int j = 0; j < 8; j++) {
            int cc = col0 + wn + 8 * j + 2 * c;
            #pragma unroll
            for (int hh = 0; hh < 2; hh++) {
                int rr = r + hh * 8;
                if (rr < M) {
                    float v0 = acc[i][j][hh * 2 + 0];
                    float v1 = acc[i][j][hh * 2 + 1];
                    float* cp = C + (size_t)rr * N + cc;
                    if (nEven) {
                        if (cc + 1 < N) {
                            if (BIAS) { v0 += bias[cc]; v1 += bias[cc + 1]; }
                            if (RELU) { v0 = fmaxf(v0, 0.f); v1 = fmaxf(v1, 0.f); }
                            *(float2*)cp = make_float2(v0, v1);
                        } else if (cc < N) {
                            if (BIAS) v0 += bias[cc];
                            if (RELU) v0 = fmaxf(v0, 0.f);
                            cp[0] = v0;
                        }
                    } else {
                        if (cc < N) {
                            if (BIAS) v0 += bias[cc];
                            if (RELU) v0 = fmaxf(v0, 0.f);
                            cp[0] = v0;
                        }
                        if (cc + 1 < N) {
                            if (BIAS) v1 += bias[cc + 1];
                            if (RELU) v1 = fmaxf(v1, 0.f);
                            cp[1] = v1;
                        }
                    }
                }
            }
        }
    }
}

// ---------------- attention + aggregation (warp per dst node) --------------
__global__ void attn_kernel() {
    int node = blockIdx.x * (blockDim.x >> 5) + (threadIdx.x >> 5);
    if (node >= NN) return;
    int lane = threadIdx.x & 31;
    const float* qkv = g_t;
    float4 qv = ((const float4*)(qkv + (size_t)node * 384))[lane];
    float s = 0.f;
    float4 acc = make_float4(0.f, 0.f, 0.f, 0.f);
    int e0 = g_off[node], e1 = g_off[node + 1];
    int e = e0;
    for (; e + 2 <= e1; e += 2) {
        const float* b0p = qkv + (size_t)g_csr[e] * 384;
        const float* b1p = qkv + (size_t)g_csr[e + 1] * 384;
        float4 k0 = ((const float4*)(b0p + 128))[lane];
        float4 v0 = ((const float4*)(b0p + 256))[lane];
        float4 k1 = ((const float4*)(b1p + 128))[lane];
        float4 v1 = ((const float4*)(b1p + 256))[lane];
        float p0 = qv.x * k0.x + qv.y * k0.y + qv.z * k0.z + qv.w * k0.w;
        float p1 = qv.x * k1.x + qv.y * k1.y + qv.z * k1.z + qv.w * k1.w;
        p0 += __shfl_xor_sync(0xFFFFFFFFu, p0, 1);
        p0 += __shfl_xor_sync(0xFFFFFFFFu, p0, 2);
        p1 += __shfl_xor_sync(0xFFFFFFFFu, p1, 1);
        p1 += __shfl_xor_sync(0xFFFFFFFFu, p1, 2);
        float w0 = __expf(p0 * 0.25f);
        float w1 = __expf(p1 * 0.25f);
        s += w0 + w1;
        acc.x += w0 * v0.x + w1 * v1.x;
        acc.y += w0 * v0.y + w1 * v1.y;
        acc.z += w0 * v0.z + w1 * v1.z;
        acc.w += w0 * v0.w + w1 * v1.w;
    }
    if (e < e1) {
        const float* b0p = qkv + (size_t)g_csr[e] * 384;
        float4 k0 = ((const float4*)(b0p + 128))[lane];
        float4 v0 = ((const float4*)(b0p + 256))[lane];
        float p0 = qv.x * k0.x + qv.y * k0.y + qv.z * k0.z + qv.w * k0.w;
        p0 += __shfl_xor_sync(0xFFFFFFFFu, p0, 1);
        p0 += __shfl_xor_sync(0xFFFFFFFFu, p0, 2);
        float w0 = __expf(p0 * 0.25f);
        s += w0;
        acc.x += w0 * v0.x; acc.y += w0 * v0.y;
        acc.z += w0 * v0.z; acc.w += w0 * v0.w;
    }
    float inv = (s > 0.f) ? 1.f / s : 0.f;
    float4 o = make_float4(acc.x * inv, acc.y * inv, acc.z * inv, acc.w * inv);
    ((float4*)(g_agg + (size_t)node * DD))[lane] = o;
}

// ---------------- host-side launch -----------------------------------------
static inline void run_gemm(int bias, int relu, const float* A, const float* B,
                            const float* bp, float* C, int M, int N, int K) {
    dim3 grid((N + 127) / 128, (M + 127) / 128);
    if (bias && relu)
        tf32gemm_kernel<1, 1, 0><<<grid, 256, GEMM_SMEM_BYTES>>>(
            A, B, bp, C, M, N, K, nullptr, nullptr, nullptr);
    else if (bias)
        tf32gemm_kernel<1, 0, 0><<<grid, 256, GEMM_SMEM_BYTES>>>(
            A, B, bp, C, M, N, K, nullptr, nullptr, nullptr);
    else
        tf32gemm_kernel<0, 0, 0><<<grid, 256, GEMM_SMEM_BYTES>>>(
            A, B, bp, C, M, N, K, nullptr, nullptr, nullptr);
}

extern "C" void kernel_launch(void* const* d_in, const int* in_sizes, int n_in,
                              void* d_out, int out_size) {
    const float* X        = (const float*)d_in[0];
    const int*   ei       = (const int*)d_in[1];
    const float* emb_w    = (const float*)d_in[2];
    const float* emb_b    = (const float*)d_in[3];
    const float* emb_ln_g = (const float*)d_in[4];
    const float* emb_ln_b = (const float*)d_in[5];
    const float* Wq       = (const float*)d_in[6];
    const float* Wk       = (const float*)d_in[7];
    const float* Wv       = (const float*)d_in[8];
    const float* Wo       = (const float*)d_in[9];
    const float* ln_g     = (const float*)d_in[10];
    const float* ln_b     = (const float*)d_in[11];
    const float* f1_w     = (const float*)d_in[12];
    const float* f1_b     = (const float*)d_in[13];
    const float* f2_w     = (const float*)d_in[14];
    const float* f2_b     = (const float*)d_in[15];
    const float* f3_w     = (const float*)d_in[16];
    const float* f3_b     = (const float*)d_in[17];
    float* out = (float*)d_out;

    const int* src = ei;
    const int* dst = ei + EE;

    cudaFuncSetAttribute(tf32gemm_kernel<1, 1, 0>,
                         cudaFuncAttributeMaxDynamicSharedMemorySize, GEMM_SMEM_BYTES);
    cudaFuncSetAttribute(tf32gemm_kernel<1, 0, 0>,
                         cudaFuncAttributeMaxDynamicSharedMemorySize, GEMM_SMEM_BYTES);
    cudaFuncSetAttribute(tf32gemm_kernel<0, 0, 0>,
                         cudaFuncAttributeMaxDynamicSharedMemorySize, GEMM_SMEM_BYTES);
    cudaFuncSetAttribute(tf32gemm_kernel<1, 1, 1>,
                         cudaFuncAttributeMaxDynamicSharedMemorySize, GEMM_SMEM_BYTES);
    cudaFuncSetAttribute(tf32gemm_kernel<0, 0, 1>,
                         cudaFuncAttributeMaxDynamicSharedMemorySize, GEMM_SMEM_BYTES);

    float *p_h, *p_agg, *p_t, *p_t2, *p_wqkv;
    cudaGetSymbolAddress((void**)&p_h,    g_h);
    cudaGetSymbolAddress((void**)&p_agg,  g_agg);
    cudaGetSymbolAddress((void**)&p_t,    g_t);
    cudaGetSymbolAddress((void**)&p_t2,   g_t2);
    cudaGetSymbolAddress((void**)&p_wqkv, g_wqkv);

    // ---- CSR build (by dst) + weight packing ----
    zero_deg_kernel<<<(NN + 255) / 256, 256>>>();
    count_deg_kernel<<<(EE + 255) / 256, 256>>>(dst);
    scan_kernel<<<1, 1024>>>();
    scatter_kernel<<<(EE + 255) / 256, 256>>>(src, dst);
    pack_qkv_kernel<<<(LL * DD * DD + 255) / 256, 256>>>(Wq, Wk, Wv);

    // ---- embedding: LN(relu(X @ emb_w + b)) -> h, fused epilogue ----
    {
        dim3 grid(1, (NN + 127) / 128);
        tf32gemm_kernel<1, 1, 1><<<grid, 256, GEMM_SMEM_BYTES>>>(
            X, emb_w, emb_b, p_h, NN, DD, DIN, nullptr, emb_ln_g, emb_ln_b);
    }

    // ---- layers ----
    for (int l = 0; l < LL; l++) {
        const float* wo = Wo + (size_t)l * DD * DD;
        run_gemm(0, 0, p_h, p_wqkv + (size_t)l * DD * 384, nullptr, p_t, NN, 384, DD);
        attn_kernel<<<(NN + 7) / 8, 256>>>();
        // h = LN(h + agg @ Wo), fused residual+LN epilogue (in-place on p_h)
        dim3 grid(1, (NN + 127) / 128);
        tf32gemm_kernel<0, 0, 1><<<grid, 256, GEMM_SMEM_BYTES>>>(
            p_agg, wo, nullptr, p_h, NN, DD, DD, p_h, ln_g + l * DD, ln_b + l * DD);
    }

    // ---- MLP head ----
    run_gemm(1, 1, p_h,  f1_w, f1_b, p_t,  NN, 512, DD);
    run_gemm(1, 1, p_t,  f2_w, f2_b, p_t2, NN, 512, 512);
    run_gemm(1, 0, p_t2, f3_w, f3_b, out,  NN, NCC, 512);
}